// round 2
// baseline (speedup 1.0000x reference)
#include <cuda_runtime.h>

#define NA 256
#define NB 256
#define NV 12
#define ND 512
#define NC 8
#define NW 64
#define NH 256
#define TEMP_INV 0.2f

// ---- scratch (no allocations allowed) ----
__device__ float g_P[NB * NV * NC * NH];   // 25 MB  [b][v][c][h]
__device__ float g_T[NA * NC * NH];        // 2 MB   [a][c][h], b1 folded in
__device__ float g_invn[NA * NC];          // 1/||t_chunk||
__device__ float g_G[NB * NC * NV * NV];   // 1.2 MB chunk Gram

// ---------------- kernel 1: Tpart + text chunk inverse norms ----------------
__global__ __launch_bounds__(256) void k_text(const float* __restrict__ text,
                                              const float* __restrict__ W1,
                                              const float* __restrict__ b1) {
    __shared__ float trow[ND];
    const int a = blockIdx.x, t = threadIdx.x;
    trow[t]       = text[a * ND + t];
    trow[t + 256] = text[a * ND + 256 + t];
    __syncthreads();

    float w1t[NW];
#pragma unroll
    for (int w = 0; w < NW; w++) w1t[w] = __ldg(&W1[w * NH + t]);
    const float bb = __ldg(&b1[t]);

#pragma unroll
    for (int c = 0; c < NC; c++) {
        float acc = bb;
#pragma unroll
        for (int w = 0; w < NW; w++) acc = fmaf(trow[c * NW + w], w1t[w], acc);
        g_T[(a * NC + c) * NH + t] = acc;
    }

    const int wid = t >> 5, lane = t & 31;
    float x1 = trow[wid * NW + lane];
    float x2 = trow[wid * NW + 32 + lane];
    float s = x1 * x1 + x2 * x2;
#pragma unroll
    for (int off = 16; off; off >>= 1) s += __shfl_xor_sync(0xffffffffu, s, off);
    if (lane == 0) g_invn[a * NC + wid] = rsqrtf(s);
}

// ---------------- kernel 2: P[b,v,c,h] = video_chunk @ W1_video ----------------
__global__ __launch_bounds__(256) void k_p(const float* __restrict__ video,
                                           const float* __restrict__ W1) {
    __shared__ float vrow[ND];
    const int v = blockIdx.x, b = blockIdx.y, t = threadIdx.x;
    const float* src = video + (b * NV + v) * ND;
    vrow[t]       = src[t];
    vrow[t + 256] = src[t + 256];
    __syncthreads();

    float w1v[NW];
#pragma unroll
    for (int w = 0; w < NW; w++) w1v[w] = __ldg(&W1[(NW + w) * NH + t]);

#pragma unroll
    for (int c = 0; c < NC; c++) {
        float acc = 0.0f;
#pragma unroll
        for (int w = 0; w < NW; w++) acc = fmaf(vrow[c * NW + w], w1v[w], acc);
        g_P[((b * NV + v) * NC + c) * NH + t] = acc;
    }
}

// ---------------- kernel 3: per-video chunk Gram matrices ----------------
__global__ __launch_bounds__(256) void k_gram(const float* __restrict__ video) {
    __shared__ float vid_sh[NV * ND];  // 24 KB
    const int b = blockIdx.x, t = threadIdx.x;
    for (int i = t; i < NV * ND; i += 256) vid_sh[i] = video[b * NV * ND + i];
    __syncthreads();
    for (int idx = t; idx < NC * NV * NV; idx += 256) {
        int c  = idx / (NV * NV);
        int r  = idx % (NV * NV);
        int v1 = r / NV, v2 = r % NV;
        const float* p1 = vid_sh + v1 * ND + c * NW;
        const float* p2 = vid_sh + v2 * ND + c * NW;
        float acc = 0.0f;
#pragma unroll
        for (int w = 0; w < NW; w++) acc = fmaf(p1[w], p2[w], acc);
        g_G[b * NC * NV * NV + idx] = acc;
    }
}

// ---------------- kernel 4: fused scores+softmax+MLP+cosine ----------------
// grid (4, NB): 64 a's per block, one b. 256 threads: warp = center c, lane owns
// hidden units {lane + 32k}. P[b] register-resident.
__global__ __launch_bounds__(256, 1) void k_main(const float* __restrict__ text,
                                                 const float* __restrict__ video,
                                                 const float* __restrict__ W2,
                                                 const float* __restrict__ b2,
                                                 float* __restrict__ out) {
    __shared__ __align__(16) float vid_sh[6 * ND];   // 12 KB (half the frames at a time)
    __shared__ float S_sh[64][NV][NC];               // 24 KB chunk dots
    __shared__ float G_sh[NC][NV][NV];               // 4.6 KB
    __shared__ float w_sh[64][NV];                   // softmax weights
    __shared__ float invn_sh[64 * NC];
    __shared__ float part_sh[64][NC];

    const int t = threadIdx.x;
    const int b = blockIdx.y;
    const int a0 = blockIdx.x * 64;
    const int lane = t & 31, c_w = t >> 5;  // warp's center

    for (int i = t; i < NC * NV * NV; i += 256)
        (&G_sh[0][0][0])[i] = g_G[b * NC * NV * NV + i];
    for (int i = t; i < 64 * NC; i += 256)
        invn_sh[i] = g_invn[a0 * NC + i];

    // ---- Phase A: S[a,v,c] = dot(t_chunk, video_chunk); frames in two halves ----
    const int al = t >> 2, sub = t & 3;  // thread covers a=al, centers {2sub,2sub+1}
    const float* trow = text + (a0 + al) * ND;
    for (int h = 0; h < 2; h++) {
        __syncthreads();
        for (int i = t; i < 6 * ND; i += 256)
            vid_sh[i] = video[(b * NV + h * 6) * ND + i];
        __syncthreads();
#pragma unroll
        for (int cc = 0; cc < 2; cc++) {
            int c = sub * 2 + cc;
            float4 tr[16];
            const float4* tp = (const float4*)(trow + c * NW);
#pragma unroll
            for (int q = 0; q < 16; q++) tr[q] = __ldg(tp + q);
#pragma unroll
            for (int vv = 0; vv < 6; vv++) {
                const float4* vb = (const float4*)(vid_sh + vv * ND + c * NW);
                float acc = 0.0f;
#pragma unroll
                for (int q = 0; q < 16; q++) {
                    float4 x = vb[q];
                    acc = fmaf(tr[q].x, x.x, acc);
                    acc = fmaf(tr[q].y, x.y, acc);
                    acc = fmaf(tr[q].z, x.z, acc);
                    acc = fmaf(tr[q].w, x.w, acc);
                }
                S_sh[al][h * 6 + vv][c] = acc;
            }
        }
    }
    __syncthreads();

    // ---- softmax over v (temp 5), one thread per a ----
    if (t < 64) {
        float s[NV], m = -1e30f;
#pragma unroll
        for (int v = 0; v < NV; v++) {
            float sum = 0.0f;
#pragma unroll
            for (int c = 0; c < NC; c++) sum += S_sh[t][v][c];
            s[v] = sum * TEMP_INV;
            m = fmaxf(m, s[v]);
        }
        float tot = 0.0f;
#pragma unroll
        for (int v = 0; v < NV; v++) { s[v] = __expf(s[v] - m); tot += s[v]; }
        float inv = 1.0f / tot;
#pragma unroll
        for (int v = 0; v < NV; v++) w_sh[t][v] = s[v] * inv;
    }

    // ---- preload P[b, :, c_w, lane+32k] and W2 into registers ----
    float p[NV][8];
#pragma unroll
    for (int v = 0; v < NV; v++)
#pragma unroll
        for (int k = 0; k < 8; k++)
            p[v][k] = g_P[((b * NV + v) * NC + c_w) * NH + lane + 32 * k];
    float w2r[8];
#pragma unroll
    for (int k = 0; k < 8; k++) w2r[k] = __ldg(&W2[lane + 32 * k]);
    const float b2v = __ldg(&b2[0]);
    __syncthreads();

    // ---- main loop over the 64 a's ----
    for (int ia = 0; ia < 64; ia++) {
        float acc[8];
        const float* tp = &g_T[((a0 + ia) * NC + c_w) * NH + lane];
#pragma unroll
        for (int k = 0; k < 8; k++) acc[k] = tp[32 * k];
#pragma unroll
        for (int v = 0; v < NV; v++) {
            float wv = w_sh[ia][v];
#pragma unroll
            for (int k = 0; k < 8; k++) acc[k] = fmaf(wv, p[v][k], acc[k]);
        }
        float g = 0.0f;
#pragma unroll
        for (int k = 0; k < 8; k++) g = fmaf(fmaxf(acc[k], 0.0f), w2r[k], g);

        float num = 0.0f, den = 0.0f;
        if (lane < NV) {
            float wl = w_sh[ia][lane];
            num = wl * S_sh[ia][lane][c_w];
            float dsum = 0.0f;
#pragma unroll
            for (int v2 = 0; v2 < NV; v2++)
                dsum = fmaf(w_sh[ia][v2], G_sh[c_w][lane][v2], dsum);
            den = wl * dsum;
        }
#pragma unroll
        for (int off = 16; off; off >>= 1) {
            g   += __shfl_xor_sync(0xffffffffu, g, off);
            num += __shfl_xor_sync(0xffffffffu, num, off);
            den += __shfl_xor_sync(0xffffffffu, den, off);
        }
        if (lane == 0) {
            float cosv = num * invn_sh[ia * NC + c_w] * rsqrtf(den);
            part_sh[ia][c_w] = cosv * (g + b2v);
        }
    }
    __syncthreads();
    if (t < 64) {
        float sum = 0.0f;
#pragma unroll
        for (int c2 = 0; c2 < NC; c2++) sum += part_sh[t][c2];
        out[(a0 + t) * NB + b] = sum;
    }
}

extern "C" void kernel_launch(void* const* d_in, const int* in_sizes, int n_in,
                              void* d_out, int out_size) {
    const float* text  = (const float*)d_in[0];
    const float* video = (const float*)d_in[1];
    const float* W1    = (const float*)d_in[2];
    const float* b1    = (const float*)d_in[3];
    const float* W2    = (const float*)d_in[4];
    const float* b2    = (const float*)d_in[5];
    float* out = (float*)d_out;

    k_text<<<NA, 256>>>(text, W1, b1);
    k_p<<<dim3(NV, NB), 256>>>(video, W1);
    k_gram<<<NB, 256>>>(video);
    k_main<<<dim3(4, NB), 256>>>(text, video, W2, b2, out);
}

// round 3
// speedup vs baseline: 1.1469x; 1.1469x over previous
#include <cuda_runtime.h>

#define NA 256
#define NB 256
#define NV 12
#define ND 512
#define NC 8
#define NW 64
#define NH 256
#define TEMP_INV 0.2f

// ---- scratch (device globals; no allocation allowed) ----
__device__ __align__(16) float g_P[NB * NV * NC * NH];   // 25 MB [b][v][c][h]
__device__ __align__(16) float g_T[NA * NC * NH];        // 2 MB  [a][c][lane][k] packed
__device__ float g_invn[NA * NC];                        // 1/||t_chunk||
__device__ float g_G[NB * NC * NV * NV];                 // 1.2 MB chunk Gram
__device__ __align__(16) float g_w[NB * NA * NV];        // 3 MB softmax weights
__device__ __align__(16) float g_cos[NB * NA * NC];      // 2 MB cosine logits

// ---------------- kernel 1: Tpart (packed layout) + text chunk inv norms ----------------
// g_T layout: g_T[a*2048 + c*256 + lane*8 + k], where hidden h = 32*k + lane.
__global__ __launch_bounds__(256) void k_text(const float* __restrict__ text,
                                              const float* __restrict__ W1,
                                              const float* __restrict__ b1) {
    __shared__ float trow[ND];
    __shared__ float stage[NC][264];  // [c][k*33+lane], padded vs 8-way conflicts
    const int a = blockIdx.x, t = threadIdx.x;
    trow[t]       = text[a * ND + t];
    trow[t + 256] = text[a * ND + 256 + t];
    __syncthreads();

    float w1t[NW];
#pragma unroll
    for (int w = 0; w < NW; w++) w1t[w] = __ldg(&W1[w * NH + t]);
    const float bb = __ldg(&b1[t]);
    const int kk = t >> 5, lane = t & 31;  // h = t = 32*kk + lane

#pragma unroll
    for (int c = 0; c < NC; c++) {
        float acc = bb;
#pragma unroll
        for (int w = 0; w < NW; w++) acc = fmaf(trow[c * NW + w], w1t[w], acc);
        stage[c][kk * 33 + lane] = acc;
    }

    // chunk inverse norms (warp kk handles chunk kk)
    float x1 = trow[kk * NW + lane];
    float x2 = trow[kk * NW + 32 + lane];
    float s = x1 * x1 + x2 * x2;
#pragma unroll
    for (int off = 16; off; off >>= 1) s += __shfl_xor_sync(0xffffffffu, s, off);
    if (lane == 0) g_invn[a * NC + kk] = rsqrtf(s);
    __syncthreads();

    // coalesced packed write
    for (int i = t; i < NC * NH; i += 256) {
        int c = i >> 8, r = i & 255;
        g_T[a * (NC * NH) + i] = stage[c][(r & 7) * 33 + (r >> 3)];
    }
}

// ---------------- kernel 2: P[b,v,c,h] = video_chunk @ W1_video ----------------
__global__ __launch_bounds__(256) void k_p(const float* __restrict__ video,
                                           const float* __restrict__ W1) {
    __shared__ float vrow[ND];
    const int v = blockIdx.x, b = blockIdx.y, t = threadIdx.x;
    const float* src = video + (b * NV + v) * ND;
    vrow[t]       = src[t];
    vrow[t + 256] = src[t + 256];
    __syncthreads();

    float w1v[NW];
#pragma unroll
    for (int w = 0; w < NW; w++) w1v[w] = __ldg(&W1[(NW + w) * NH + t]);

#pragma unroll
    for (int c = 0; c < NC; c++) {
        float acc = 0.0f;
#pragma unroll
        for (int w = 0; w < NW; w++) acc = fmaf(vrow[c * NW + w], w1v[w], acc);
        g_P[((b * NV + v) * NC + c) * NH + t] = acc;
    }
}

// ---------------- kernel 3: per-video chunk Gram ----------------
__global__ __launch_bounds__(256) void k_gram(const float* __restrict__ video) {
    __shared__ float vid_sh[NV * ND];
    const int b = blockIdx.x, t = threadIdx.x;
    for (int i = t; i < NV * ND; i += 256) vid_sh[i] = video[b * NV * ND + i];
    __syncthreads();
    for (int idx = t; idx < NC * NV * NV; idx += 256) {
        int c  = idx / (NV * NV);
        int r  = idx % (NV * NV);
        int v1 = r / NV, v2 = r % NV;
        const float* p1 = vid_sh + v1 * ND + c * NW;
        const float* p2 = vid_sh + v2 * ND + c * NW;
        float acc = 0.0f;
#pragma unroll
        for (int w = 0; w < NW; w++) acc = fmaf(p1[w], p2[w], acc);
        g_G[b * NC * NV * NV + idx] = acc;
    }
}

// ---------------- kernel 4: scores + softmax + cosine logits ----------------
// grid (4, NB), 256 threads. Writes g_w and g_cos.
__global__ __launch_bounds__(256) void k_score(const float* __restrict__ text,
                                               const float* __restrict__ video) {
    __shared__ __align__(16) float vid_sh[6 * ND];
    __shared__ float S_sh[64][NV][NC];
    __shared__ float G_sh[NC][NV][NV];
    __shared__ float w_sh[64][NV];
    __shared__ float invn_sh[64 * NC];

    const int t = threadIdx.x;
    const int b = blockIdx.y;
    const int a0 = blockIdx.x * 64;

    for (int i = t; i < NC * NV * NV; i += 256)
        (&G_sh[0][0][0])[i] = g_G[b * NC * NV * NV + i];
    for (int i = t; i < 64 * NC; i += 256)
        invn_sh[i] = g_invn[a0 * NC + i];

    const int al = t >> 2, sub = t & 3;
    const float* trow = text + (a0 + al) * ND;
    for (int h = 0; h < 2; h++) {
        __syncthreads();
        for (int i = t; i < 6 * ND; i += 256)
            vid_sh[i] = video[(b * NV + h * 6) * ND + i];
        __syncthreads();
#pragma unroll
        for (int cc = 0; cc < 2; cc++) {
            int c = sub * 2 + cc;
            float4 tr[16];
            const float4* tp = (const float4*)(trow + c * NW);
#pragma unroll
            for (int q = 0; q < 16; q++) tr[q] = __ldg(tp + q);
#pragma unroll
            for (int vv = 0; vv < 6; vv++) {
                const float4* vb = (const float4*)(vid_sh + vv * ND + c * NW);
                float acc = 0.0f;
#pragma unroll
                for (int q = 0; q < 16; q++) {
                    float4 x = vb[q];
                    acc = fmaf(tr[q].x, x.x, acc);
                    acc = fmaf(tr[q].y, x.y, acc);
                    acc = fmaf(tr[q].z, x.z, acc);
                    acc = fmaf(tr[q].w, x.w, acc);
                }
                S_sh[al][h * 6 + vv][c] = acc;
            }
        }
    }
    __syncthreads();

    if (t < 64) {
        float s[NV], m = -1e30f;
#pragma unroll
        for (int v = 0; v < NV; v++) {
            float sum = 0.0f;
#pragma unroll
            for (int c = 0; c < NC; c++) sum += S_sh[t][v][c];
            s[v] = sum * TEMP_INV;
            m = fmaxf(m, s[v]);
        }
        float tot = 0.0f;
#pragma unroll
        for (int v = 0; v < NV; v++) { s[v] = __expf(s[v] - m); tot += s[v]; }
        float inv = 1.0f / tot;
#pragma unroll
        for (int v = 0; v < NV; v++) w_sh[t][v] = s[v] * inv;
    }
    __syncthreads();

    // cosine logits: 512 (a,c) tasks over 256 threads
    for (int idx = t; idx < 512; idx += 256) {
        int aa = idx >> 3, cc = idx & 7;
        float wv[NV];
#pragma unroll
        for (int v = 0; v < NV; v++) wv[v] = w_sh[aa][v];
        float num = 0.0f, den = 0.0f;
#pragma unroll
        for (int v = 0; v < NV; v++) num = fmaf(wv[v], S_sh[aa][v][cc], num);
#pragma unroll
        for (int v1 = 0; v1 < NV; v1++) {
            float ds = 0.0f;
#pragma unroll
            for (int v2 = 0; v2 < NV; v2++) ds = fmaf(wv[v2], G_sh[cc][v1][v2], ds);
            den = fmaf(wv[v1], ds, den);
        }
        g_cos[(b * NA + a0 + aa) * NC + cc] = num * invn_sh[aa * NC + cc] * rsqrtf(den);
    }
    for (int i = t; i < 64 * NV; i += 256)
        g_w[(b * NA + a0) * NV + i] = (&w_sh[0][0])[i];
}

// ---------------- kernel 5: MLP gating main loop ----------------
// grid (4, NB), 512 threads. warp = (center, half); lane owns h = 32*(half*4+j)+lane.
__global__ __launch_bounds__(512, 1) void k_main(const float* __restrict__ W2,
                                                 const float* __restrict__ b2,
                                                 float* __restrict__ out) {
    __shared__ __align__(16) float w_sh[64][12];
    __shared__ float cos_sh[64][NC];
    __shared__ float part_sh[64][16];

    const int t = threadIdx.x;
    const int b = blockIdx.y;
    const int a0 = blockIdx.x * 64;
    const int lane = t & 31, w16 = t >> 5;
    const int c = w16 >> 1, half = w16 & 1;

    for (int i = t; i < 64 * NV; i += 512)
        (&w_sh[0][0])[i] = g_w[(b * NA + a0) * NV + i];
    for (int i = t; i < 64 * NC; i += 512)
        (&cos_sh[0][0])[i] = g_cos[(b * NA + a0) * NC + i];

    float p[NV][4];
#pragma unroll
    for (int v = 0; v < NV; v++)
#pragma unroll
        for (int j = 0; j < 4; j++)
            p[v][j] = g_P[((b * NV + v) * NC + c) * NH + 32 * (half * 4 + j) + lane];
    float w2r[4];
#pragma unroll
    for (int j = 0; j < 4; j++) w2r[j] = __ldg(&W2[32 * (half * 4 + j) + lane]);
    const float b2v = __ldg(&b2[0]);
    __syncthreads();

    const float* tb = g_T + (a0 * NC + c) * NH + lane * 8 + half * 4;
    float4 tn = *(const float4*)tb;

    for (int ia = 0; ia < 64; ia++) {
        float acc0 = tn.x, acc1 = tn.y, acc2 = tn.z, acc3 = tn.w;
        int nia = (ia < 63) ? ia + 1 : 63;
        tn = *(const float4*)(tb + nia * (NC * NH));  // prefetch next a

        const float4* wr = (const float4*)w_sh[ia];
        float4 wA = wr[0], wB = wr[1], wC = wr[2];
#define STEP(WV, V)                                   \
        acc0 = fmaf(WV, p[V][0], acc0);               \
        acc1 = fmaf(WV, p[V][1], acc1);               \
        acc2 = fmaf(WV, p[V][2], acc2);               \
        acc3 = fmaf(WV, p[V][3], acc3);
        STEP(wA.x, 0) STEP(wA.y, 1) STEP(wA.z, 2) STEP(wA.w, 3)
        STEP(wB.x, 4) STEP(wB.y, 5) STEP(wB.z, 6) STEP(wB.w, 7)
        STEP(wC.x, 8) STEP(wC.y, 9) STEP(wC.z, 10) STEP(wC.w, 11)
#undef STEP
        float g = fmaxf(acc0, 0.0f) * w2r[0];
        g = fmaf(fmaxf(acc1, 0.0f), w2r[1], g);
        g = fmaf(fmaxf(acc2, 0.0f), w2r[2], g);
        g = fmaf(fmaxf(acc3, 0.0f), w2r[3], g);
#pragma unroll
        for (int off = 16; off; off >>= 1) g += __shfl_xor_sync(0xffffffffu, g, off);
        if (lane == 0) part_sh[ia][c * 2 + half] = g;
    }
    __syncthreads();

    if (t < 64) {
        float sum = 0.0f;
#pragma unroll
        for (int c2 = 0; c2 < NC; c2++)
            sum += (part_sh[t][2 * c2] + part_sh[t][2 * c2 + 1] + b2v) * cos_sh[t][c2];
        out[(a0 + t) * NB + b] = sum;
    }
}

extern "C" void kernel_launch(void* const* d_in, const int* in_sizes, int n_in,
                              void* d_out, int out_size) {
    const float* text  = (const float*)d_in[0];
    const float* video = (const float*)d_in[1];
    const float* W1    = (const float*)d_in[2];
    const float* b1    = (const float*)d_in[3];
    const float* W2    = (const float*)d_in[4];
    const float* b2    = (const float*)d_in[5];
    float* out = (float*)d_out;

    k_text<<<NA, 256>>>(text, W1, b1);
    k_p<<<dim3(NV, NB), 256>>>(video, W1);
    k_gram<<<NB, 256>>>(video);
    k_score<<<dim3(4, NB), 256>>>(text, video);
    k_main<<<dim3(4, NB), 512>>>(W2, b2, out);
}

// round 4
// speedup vs baseline: 1.7780x; 1.5502x over previous
#include <cuda_runtime.h>

#define NA 256
#define NB 256
#define NV 12
#define ND 512
#define NC 8
#define NW 64
#define NH 256
#define TEMP_INV 0.2f

// ---- scratch (device globals; no allocation allowed) ----
__device__ __align__(16) float g_P[NB * NV * NC * NH];   // 25 MB [b][v][c][h]
__device__ __align__(16) float g_T[NA * NC * NH];        // 2 MB  [a][c][lane*8+k] packed
__device__ float g_invn[NA * NC];                        // 1/||t_chunk||
__device__ float g_G[NB * NC * NV * NV];                 // 1.2 MB chunk Gram
__device__ __align__(16) float g_w[NB * NA * NV];        // 3 MB softmax weights
__device__ __align__(16) float g_cos[NB * NA * NC];      // 2 MB cosine logits

// ---- packed f32x2 helpers ----
__device__ __forceinline__ unsigned long long pk2(float lo, float hi) {
    unsigned long long r;
    asm("mov.b64 %0, {%1, %2};" : "=l"(r) : "f"(lo), "f"(hi));
    return r;
}
__device__ __forceinline__ void upk2(unsigned long long p, float& lo, float& hi) {
    asm("mov.b64 {%0, %1}, %2;" : "=f"(lo), "=f"(hi) : "l"(p));
}
__device__ __forceinline__ unsigned long long ffma2(unsigned long long a, unsigned long long b,
                                                    unsigned long long c) {
    unsigned long long d;
    asm("fma.rn.f32x2 %0, %1, %2, %3;" : "=l"(d) : "l"(a), "l"(b), "l"(c));
    return d;
}

// ---------------- kernel 1: Tpart (packed layout) + text chunk inv norms ----------------
// g_T layout: g_T[a*2048 + c*256 + lane*8 + k], where hidden h = 32*k + lane.
__global__ __launch_bounds__(256) void k_text(const float* __restrict__ text,
                                              const float* __restrict__ W1,
                                              const float* __restrict__ b1) {
    __shared__ float trow[ND];
    __shared__ float stage[NC][264];
    const int a = blockIdx.x, t = threadIdx.x;
    trow[t]       = text[a * ND + t];
    trow[t + 256] = text[a * ND + 256 + t];
    __syncthreads();

    float w1t[NW];
#pragma unroll
    for (int w = 0; w < NW; w++) w1t[w] = __ldg(&W1[w * NH + t]);
    const float bb = __ldg(&b1[t]);
    const int kk = t >> 5, lane = t & 31;

#pragma unroll
    for (int c = 0; c < NC; c++) {
        float acc = bb;
#pragma unroll
        for (int w = 0; w < NW; w++) acc = fmaf(trow[c * NW + w], w1t[w], acc);
        stage[c][kk * 33 + lane] = acc;
    }

    float x1 = trow[kk * NW + lane];
    float x2 = trow[kk * NW + 32 + lane];
    float s = x1 * x1 + x2 * x2;
#pragma unroll
    for (int off = 16; off; off >>= 1) s += __shfl_xor_sync(0xffffffffu, s, off);
    if (lane == 0) g_invn[a * NC + kk] = rsqrtf(s);
    __syncthreads();

    for (int i = t; i < NC * NH; i += 256) {
        int c = i >> 8, r = i & 255;
        g_T[a * (NC * NH) + i] = stage[c][(r & 7) * 33 + (r >> 3)];
    }
}

// ---------------- kernel 2: P[b,v,c,h] = video_chunk @ W1_video (f32x2) ----------------
__global__ __launch_bounds__(256) void k_p(const float* __restrict__ video,
                                           const float* __restrict__ W1) {
    __shared__ __align__(16) float vrow[ND];
    const int v = blockIdx.x, b = blockIdx.y, t = threadIdx.x;
    const float* src = video + (b * NV + v) * ND;
    vrow[t]       = src[t];
    vrow[t + 256] = src[t + 256];
    __syncthreads();

    unsigned long long w1p[NW / 2];  // packed pairs over w
#pragma unroll
    for (int w = 0; w < NW / 2; w++)
        w1p[w] = pk2(__ldg(&W1[(NW + 2 * w) * NH + t]), __ldg(&W1[(NW + 2 * w + 1) * NH + t]));

#pragma unroll
    for (int c = 0; c < NC; c++) {
        unsigned long long accA = 0ULL, accB = 0ULL;
        const ulonglong2* vr = (const ulonglong2*)(vrow + c * NW);
#pragma unroll
        for (int q = 0; q < NW / 4; q++) {
            ulonglong2 x = vr[q];
            accA = ffma2(x.x, w1p[2 * q], accA);
            accB = ffma2(x.y, w1p[2 * q + 1], accB);
        }
        float a0, a1, b0, b1;
        upk2(accA, a0, a1); upk2(accB, b0, b1);
        g_P[((b * NV + v) * NC + c) * NH + t] = (a0 + b0) + (a1 + b1);
    }
}

// ---------------- kernel 3: per-video chunk Gram ----------------
__global__ __launch_bounds__(256) void k_gram(const float* __restrict__ video) {
    __shared__ float vid_sh[NV * ND];
    const int b = blockIdx.x, t = threadIdx.x;
    for (int i = t; i < NV * ND; i += 256) vid_sh[i] = video[b * NV * ND + i];
    __syncthreads();
    for (int idx = t; idx < NC * NV * NV; idx += 256) {
        int c  = idx / (NV * NV);
        int r  = idx % (NV * NV);
        int v1 = r / NV, v2 = r % NV;
        const float* p1 = vid_sh + v1 * ND + c * NW;
        const float* p2 = vid_sh + v2 * ND + c * NW;
        float acc = 0.0f;
#pragma unroll
        for (int w = 0; w < NW; w++) acc = fmaf(p1[w], p2[w], acc);
        g_G[b * NC * NV * NV + idx] = acc;
    }
}

// ---------------- kernel 4: scores + softmax + cosine logits (rebuilt) ----------------
// grid (4, NB), 256 threads. Thread = (al = t&63, vg = t>>6); vg covers frames 3vg..3vg+2.
#define TROW 68
__global__ __launch_bounds__(256, 3) void k_score(const float* __restrict__ text,
                                                  const float* __restrict__ video) {
    __shared__ __align__(16) float T_sh[64 * TROW];    // 17.4 KB text chunk, padded
    __shared__ __align__(16) float V_sh[NV * NW];      // 3 KB video chunk
    __shared__ float logit_sh[64 * 13];                // 3.3 KB
    __shared__ float np_sh[64 * 33];                   // 8.4 KB num partials
    __shared__ float G_sh[NC * NV * NV];               // 4.6 KB
    __shared__ float w_sh[64 * NV];                    // 3 KB
    __shared__ float invn_sh[64 * NC];                 // 2 KB

    const int t = threadIdx.x;
    const int b = blockIdx.y;
    const int a0 = blockIdx.x * 64;
    const int al = t & 63, vg = t >> 6;

    for (int i = t; i < NC * NV * NV; i += 256) G_sh[i] = g_G[b * NC * NV * NV + i];
    for (int i = t; i < 64 * NC; i += 256) invn_sh[i] = g_invn[a0 * NC + i];

    float S[3][NC];  // per-thread chunk dots, kept in registers
    const int lrow = t >> 2, lpart = t & 3;
    const float4* tsrc = (const float4*)(text + (a0 + lrow) * ND) + lpart * 4;

#pragma unroll
    for (int c = 0; c < NC; c++) {
        __syncthreads();
        {   // stage text chunk [64 a][64 w] (coalesced; 16B-aligned padded rows)
            const float4* s = tsrc + c * 16;
            float4* d = (float4*)&T_sh[lrow * TROW + lpart * 16];
            d[0] = __ldg(s); d[1] = __ldg(s + 1); d[2] = __ldg(s + 2); d[3] = __ldg(s + 3);
        }
        if (t < 192) {  // stage video chunk [12 v][64 w]
            int v = t >> 4, part = t & 15;
            ((float4*)V_sh)[t] =
                __ldg((const float4*)(video + (b * NV + v) * ND + c * NW) + part);
        }
        __syncthreads();

        unsigned long long accA[3] = {0ULL, 0ULL, 0ULL};
        unsigned long long accB[3] = {0ULL, 0ULL, 0ULL};
#pragma unroll
        for (int q = 0; q < 16; q++) {
            ulonglong2 tr = *(const ulonglong2*)&T_sh[al * TROW + q * 4];
#pragma unroll
            for (int j = 0; j < 3; j++) {
                ulonglong2 vd = *(const ulonglong2*)&V_sh[(vg * 3 + j) * NW + q * 4];
                accA[j] = ffma2(tr.x, vd.x, accA[j]);
                accB[j] = ffma2(tr.y, vd.y, accB[j]);
            }
        }
#pragma unroll
        for (int j = 0; j < 3; j++) {
            float x0, x1, y0, y1;
            upk2(accA[j], x0, x1); upk2(accB[j], y0, y1);
            S[j][c] = (x0 + y0) + (x1 + y1);
        }
    }

    // per-frame logits (sum over centers), from registers
#pragma unroll
    for (int j = 0; j < 3; j++) {
        float l = 0.0f;
#pragma unroll
        for (int c = 0; c < NC; c++) l += S[j][c];
        logit_sh[al * 13 + vg * 3 + j] = l;
    }
    __syncthreads();

    if (t < 64) {  // softmax over v
        float s[NV], m = -1e30f;
#pragma unroll
        for (int v = 0; v < NV; v++) {
            s[v] = logit_sh[t * 13 + v] * TEMP_INV;
            m = fmaxf(m, s[v]);
        }
        float tot = 0.0f;
#pragma unroll
        for (int v = 0; v < NV; v++) { s[v] = __expf(s[v] - m); tot += s[v]; }
        float inv = 1.0f / tot;
#pragma unroll
        for (int v = 0; v < NV; v++) w_sh[t * NV + v] = s[v] * inv;
    }
    __syncthreads();

    // cosine numerator partials from register S
    {
        float wj[3];
#pragma unroll
        for (int j = 0; j < 3; j++) wj[j] = w_sh[al * NV + vg * 3 + j];
#pragma unroll
        for (int c = 0; c < NC; c++) {
            float acc = wj[0] * S[0][c];
            acc = fmaf(wj[1], S[1][c], acc);
            acc = fmaf(wj[2], S[2][c], acc);
            np_sh[al * 33 + vg * 8 + c] = acc;
        }
    }
    __syncthreads();

    // finish cosine: 512 (a,c) tasks
    for (int idx = t; idx < 512; idx += 256) {
        int aa = idx >> 3, cc = idx & 7;
        float wv[NV];
#pragma unroll
        for (int v = 0; v < NV; v++) wv[v] = w_sh[aa * NV + v];
        float num = (np_sh[aa * 33 + cc] + np_sh[aa * 33 + 8 + cc]) +
                    (np_sh[aa * 33 + 16 + cc] + np_sh[aa * 33 + 24 + cc]);
        float den = 0.0f;
#pragma unroll
        for (int v1 = 0; v1 < NV; v1++) {
            float ds = 0.0f;
#pragma unroll
            for (int v2 = 0; v2 < NV; v2++)
                ds = fmaf(wv[v2], G_sh[cc * NV * NV + v1 * NV + v2], ds);
            den = fmaf(wv[v1], ds, den);
        }
        g_cos[(b * NA + a0 + aa) * NC + cc] = num * invn_sh[aa * NC + cc] * rsqrtf(den);
    }
    for (int i = t; i < 64 * NV; i += 256) g_w[(b * NA + a0) * NV + i] = w_sh[i];
}

// ---------------- kernel 5: MLP gating main loop (f32x2) ----------------
// grid (4, NB), 512 threads. warp = (center, half); lane owns h = 32*(half*4+j)+lane.
__global__ __launch_bounds__(512, 1) void k_main(const float* __restrict__ W2,
                                                 const float* __restrict__ b2,
                                                 float* __restrict__ out) {
    __shared__ __align__(16) float2 wd_sh[64 * NV];  // duplicated packed weights, 6 KB
    __shared__ float cos_sh[64 * NC];
    __shared__ float part_sh[64][16];

    const int t = threadIdx.x;
    const int b = blockIdx.y;
    const int a0 = blockIdx.x * 64;
    const int lane = t & 31, w16 = t >> 5;
    const int c = w16 >> 1, half = w16 & 1;

    for (int i = t; i < 64 * NV; i += 512) {
        float wv = g_w[(b * NA + a0) * NV + i];
        wd_sh[i] = make_float2(wv, wv);
    }
    for (int i = t; i < 64 * NC; i += 512) cos_sh[i] = g_cos[(b * NA + a0) * NC + i];

    unsigned long long pp[NV][2];
#pragma unroll
    for (int v = 0; v < NV; v++)
#pragma unroll
        for (int jp = 0; jp < 2; jp++) {
            const float* base = &g_P[((b * NV + v) * NC + c) * NH + lane];
            pp[v][jp] = pk2(base[32 * (half * 4 + 2 * jp)], base[32 * (half * 4 + 2 * jp + 1)]);
        }
    float w2r[4];
#pragma unroll
    for (int j = 0; j < 4; j++) w2r[j] = __ldg(&W2[32 * (half * 4 + j) + lane]);
    const float b2v = __ldg(&b2[0]);
    __syncthreads();

    const float* tb = g_T + (a0 * NC + c) * NH + lane * 8 + half * 4;
    ulonglong2 tn = *(const ulonglong2*)tb;

    for (int ia = 0; ia < 64; ia++) {
        unsigned long long a01 = tn.x, a23 = tn.y;
        int nia = (ia < 63) ? ia + 1 : 63;
        tn = *(const ulonglong2*)(tb + nia * (NC * NH));  // prefetch next a

        const ulonglong2* wrow = (const ulonglong2*)&wd_sh[ia * NV];
#pragma unroll
        for (int vq = 0; vq < 6; vq++) {
            ulonglong2 wp = wrow[vq];
            a01 = ffma2(wp.x, pp[2 * vq][0], a01);
            a23 = ffma2(wp.x, pp[2 * vq][1], a23);
            a01 = ffma2(wp.y, pp[2 * vq + 1][0], a01);
            a23 = ffma2(wp.y, pp[2 * vq + 1][1], a23);
        }
        float f0, f1, f2, f3;
        upk2(a01, f0, f1); upk2(a23, f2, f3);
        float g = fmaxf(f0, 0.0f) * w2r[0];
        g = fmaf(fmaxf(f1, 0.0f), w2r[1], g);
        g = fmaf(fmaxf(f2, 0.0f), w2r[2], g);
        g = fmaf(fmaxf(f3, 0.0f), w2r[3], g);
#pragma unroll
        for (int off = 16; off; off >>= 1) g += __shfl_xor_sync(0xffffffffu, g, off);
        if (lane == 0) part_sh[ia][c * 2 + half] = g;
    }
    __syncthreads();

    if (t < 64) {
        float sum = 0.0f;
#pragma unroll
        for (int c2 = 0; c2 < NC; c2++)
            sum += (part_sh[t][2 * c2] + part_sh[t][2 * c2 + 1] + b2v) * cos_sh[t * NC + c2];
        out[(a0 + t) * NB + b] = sum;
    }
}

extern "C" void kernel_launch(void* const* d_in, const int* in_sizes, int n_in,
                              void* d_out, int out_size) {
    const float* text  = (const float*)d_in[0];
    const float* video = (const float*)d_in[1];
    const float* W1    = (const float*)d_in[2];
    const float* b1    = (const float*)d_in[3];
    const float* W2    = (const float*)d_in[4];
    const float* b2    = (const float*)d_in[5];
    float* out = (float*)d_out;

    k_text<<<NA, 256>>>(text, W1, b1);
    k_p<<<dim3(NV, NB), 256>>>(video, W1);
    k_gram<<<NB, 256>>>(video);
    k_score<<<dim3(4, NB), 256>>>(text, video);
    k_main<<<dim3(4, NB), 512>>>(W2, b2, out);
}

// round 5
// speedup vs baseline: 1.8929x; 1.0646x over previous
#include <cuda_runtime.h>
#include <cstdint>

#define NA 256
#define NB 256
#define NV 12
#define ND 512
#define NC 8
#define NW 64
#define NH 256
#define TEMP_INV 0.2f

// ---- scratch (device globals; no allocation allowed) ----
__device__ __align__(16) float g_P[NB * NV * NC * NH];   // 25 MB [b][v][c][h]
__device__ __align__(16) float g_T[NA * NC * NH];        // 2 MB  [a][c][lane*8+k] packed
__device__ float g_invn[NA * NC];                        // 1/||t_chunk||
__device__ float g_G[NB * NC * NV * NV];                 // 1.2 MB chunk Gram
__device__ __align__(16) float g_w[NB * NA * NV];        // 3 MB softmax weights
__device__ __align__(16) float g_cos[NB * NA * NC];      // 2 MB cosine logits

// ---- packed f32x2 helpers ----
__device__ __forceinline__ unsigned long long pk2(float lo, float hi) {
    unsigned long long r;
    asm("mov.b64 %0, {%1, %2};" : "=l"(r) : "f"(lo), "f"(hi));
    return r;
}
__device__ __forceinline__ void upk2(unsigned long long p, float& lo, float& hi) {
    asm("mov.b64 {%0, %1}, %2;" : "=f"(lo), "=f"(hi) : "l"(p));
}
__device__ __forceinline__ unsigned long long ffma2(unsigned long long a, unsigned long long b,
                                                    unsigned long long c) {
    unsigned long long d;
    asm("fma.rn.f32x2 %0, %1, %2, %3;" : "=l"(d) : "l"(a), "l"(b), "l"(c));
    return d;
}

// ---- cp.async helpers ----
__device__ __forceinline__ void cp16(uint32_t dst_smem, const void* src) {
    asm volatile("cp.async.cg.shared.global [%0], [%1], 16;" :: "r"(dst_smem), "l"(src));
}
__device__ __forceinline__ void cp_commit() {
    asm volatile("cp.async.commit_group;");
}
template <int N>
__device__ __forceinline__ void cp_wait() {
    asm volatile("cp.async.wait_group %0;" :: "n"(N));
}

// ================= kernel 1 (merged prologue): k_p | k_text | k_gram =================
__global__ __launch_bounds__(256) void k_pre(const float* __restrict__ text,
                                             const float* __restrict__ video,
                                             const float* __restrict__ W1,
                                             const float* __restrict__ b1) {
    __shared__ __align__(16) float sm[NV * ND];  // 24 KB, aliased per role
    const int bid = blockIdx.x, t = threadIdx.x;

    if (bid < NB * NV) {
        // ---- P[b,v,c,h] = video_chunk @ W1_video (f32x2) ----
        const int v = bid % NV, b = bid / NV;
        float* vrow = sm;
        const float* src = video + (b * NV + v) * ND;
        vrow[t]       = src[t];
        vrow[t + 256] = src[t + 256];
        __syncthreads();

        unsigned long long w1p[NW / 2];
#pragma unroll
        for (int w = 0; w < NW / 2; w++)
            w1p[w] = pk2(__ldg(&W1[(NW + 2 * w) * NH + t]),
                         __ldg(&W1[(NW + 2 * w + 1) * NH + t]));

#pragma unroll
        for (int c = 0; c < NC; c++) {
            unsigned long long accA = 0ULL, accB = 0ULL;
            const ulonglong2* vr = (const ulonglong2*)(vrow + c * NW);
#pragma unroll
            for (int q = 0; q < NW / 4; q++) {
                ulonglong2 x = vr[q];
                accA = ffma2(x.x, w1p[2 * q], accA);
                accB = ffma2(x.y, w1p[2 * q + 1], accB);
            }
            float a0, a1, b0, b1;
            upk2(accA, a0, a1); upk2(accB, b0, b1);
            g_P[((b * NV + v) * NC + c) * NH + t] = (a0 + b0) + (a1 + b1);
        }
    } else if (bid < NB * NV + NA) {
        // ---- Tpart (packed layout) + text chunk inverse norms ----
        const int a = bid - NB * NV;
        float* trow  = sm;        // 512
        float* stage = sm + 512;  // 8*264 = 2112
        trow[t]       = text[a * ND + t];
        trow[t + 256] = text[a * ND + 256 + t];
        __syncthreads();

        float w1t[NW];
#pragma unroll
        for (int w = 0; w < NW; w++) w1t[w] = __ldg(&W1[w * NH + t]);
        const float bb = __ldg(&b1[t]);
        const int kk = t >> 5, lane = t & 31;

#pragma unroll
        for (int c = 0; c < NC; c++) {
            float acc = bb;
#pragma unroll
            for (int w = 0; w < NW; w++) acc = fmaf(trow[c * NW + w], w1t[w], acc);
            stage[c * 264 + kk * 33 + lane] = acc;
        }

        float x1 = trow[kk * NW + lane];
        float x2 = trow[kk * NW + 32 + lane];
        float s = x1 * x1 + x2 * x2;
#pragma unroll
        for (int off = 16; off; off >>= 1) s += __shfl_xor_sync(0xffffffffu, s, off);
        if (lane == 0) g_invn[a * NC + kk] = rsqrtf(s);
        __syncthreads();

        for (int i = t; i < NC * NH; i += 256) {
            int c = i >> 8, r = i & 255;
            g_T[a * (NC * NH) + i] = stage[c * 264 + (r & 7) * 33 + (r >> 3)];
        }
    } else {
        // ---- per-video chunk Gram ----
        const int b = bid - NB * NV - NA;
        for (int i = t; i < NV * ND; i += 256) sm[i] = video[b * NV * ND + i];
        __syncthreads();
        for (int idx = t; idx < NC * NV * NV; idx += 256) {
            int c  = idx / (NV * NV);
            int r  = idx % (NV * NV);
            int v1 = r / NV, v2 = r % NV;
            const float* p1 = sm + v1 * ND + c * NW;
            const float* p2 = sm + v2 * ND + c * NW;
            float acc = 0.0f;
#pragma unroll
            for (int w = 0; w < NW; w++) acc = fmaf(p1[w], p2[w], acc);
            g_G[b * NC * NV * NV + idx] = acc;
        }
    }
}

// ================= kernel 2: scores + softmax + cosine (cp.async pipelined) =================
// grid (4, NB), 256 threads. Thread = (al = t&63, vg = t>>6); vg covers frames 3vg..3vg+2.
#define TROW 68
#define TBUF (64 * TROW)  // 4352 floats per buffer
// dynamic smem layout (floats):
//   [0)        T_sh   2*4352 = 8704
//   [8704)     V_sh   12*512 = 6144
//   [14848)    G_sh   1152
//   [16000)    w_sh   768
//   [16768)    invn   512
//   [17280)    logit  64*13 = 832
//   [18112)    np     64*33 = 2112
//   total 20224 floats = 80896 B
#define SCORE_SMEM_BYTES (20224 * 4)

__global__ __launch_bounds__(256, 2) void k_score(const float* __restrict__ text,
                                                  const float* __restrict__ video) {
    extern __shared__ __align__(16) float dyn[];
    float* T_sh    = dyn;
    float* V_sh    = dyn + 8704;
    float* G_sh    = dyn + 14848;
    float* w_sh    = dyn + 16000;
    float* invn_sh = dyn + 16768;
    float* logit_sh= dyn + 17280;
    float* np_sh   = dyn + 18112;

    const int t = threadIdx.x;
    const int b = blockIdx.y;
    const int a0 = blockIdx.x * 64;
    const int al = t & 63, vg = t >> 6;

    // thread's staging slots (row lrow, 16-float segment lpart)
    const int lrow = t >> 2, lpart = t & 3;
    const float* tg = text + (a0 + lrow) * ND + lpart * 16;
    uint32_t ts_addr[2];
#pragma unroll
    for (int bu = 0; bu < 2; bu++)
        ts_addr[bu] = (uint32_t)__cvta_generic_to_shared(
            &T_sh[bu * TBUF + lrow * TROW + lpart * 16]);

    // stage chunk 0 (buffer 0)
#pragma unroll
    for (int k = 0; k < 4; k++) cp16(ts_addr[0] + k * 16, tg + k * 4);
    cp_commit();

    // stage all video rows + G + invn with normal loads
    {
        const float4* vsrc = (const float4*)(video + b * NV * ND);
        float4* vdst = (float4*)V_sh;
        for (int i = t; i < NV * ND / 4; i += 256) vdst[i] = __ldg(vsrc + i);
    }
    for (int i = t; i < NC * NV * NV; i += 256) G_sh[i] = g_G[b * NC * NV * NV + i];
    for (int i = t; i < 64 * NC; i += 256) invn_sh[i] = g_invn[a0 * NC + i];

    float S[3][NC];  // per-thread chunk dots, registers
#pragma unroll
    for (int c = 0; c < NC; c++) {
        if (c < 7) {  // prefetch next chunk into other buffer
#pragma unroll
            for (int k = 0; k < 4; k++)
                cp16(ts_addr[(c + 1) & 1] + k * 16, tg + (c + 1) * 64 + k * 4);
            cp_commit();
            cp_wait<1>();
        } else {
            cp_wait<0>();
        }
        __syncthreads();

        const float* Tb = T_sh + (c & 1) * TBUF;
        unsigned long long accA[3] = {0ULL, 0ULL, 0ULL};
        unsigned long long accB[3] = {0ULL, 0ULL, 0ULL};
#pragma unroll
        for (int q = 0; q < 16; q++) {
            ulonglong2 tr = *(const ulonglong2*)&Tb[al * TROW + q * 4];
#pragma unroll
            for (int j = 0; j < 3; j++) {
                ulonglong2 vd = *(const ulonglong2*)&V_sh[(vg * 3 + j) * ND + c * NW + q * 4];
                accA[j] = ffma2(tr.x, vd.x, accA[j]);
                accB[j] = ffma2(tr.y, vd.y, accB[j]);
            }
        }
#pragma unroll
        for (int j = 0; j < 3; j++) {
            float x0, x1, y0, y1;
            upk2(accA[j], x0, x1); upk2(accB[j], y0, y1);
            S[j][c] = (x0 + y0) + (x1 + y1);
        }
        __syncthreads();  // protect buffer reuse
    }

    // per-frame logits from registers
#pragma unroll
    for (int j = 0; j < 3; j++) {
        float l = 0.0f;
#pragma unroll
        for (int c = 0; c < NC; c++) l += S[j][c];
        logit_sh[al * 13 + vg * 3 + j] = l;
    }
    __syncthreads();

    if (t < 64) {  // softmax over v
        float s[NV], m = -1e30f;
#pragma unroll
        for (int v = 0; v < NV; v++) {
            s[v] = logit_sh[t * 13 + v] * TEMP_INV;
            m = fmaxf(m, s[v]);
        }
        float tot = 0.0f;
#pragma unroll
        for (int v = 0; v < NV; v++) { s[v] = __expf(s[v] - m); tot += s[v]; }
        float inv = 1.0f / tot;
#pragma unroll
        for (int v = 0; v < NV; v++) w_sh[t * NV + v] = s[v] * inv;
    }
    __syncthreads();

    // cosine numerator partials from register S
    {
        float wj[3];
#pragma unroll
        for (int j = 0; j < 3; j++) wj[j] = w_sh[al * NV + vg * 3 + j];
#pragma unroll
        for (int c = 0; c < NC; c++) {
            float acc = wj[0] * S[0][c];
            acc = fmaf(wj[1], S[1][c], acc);
            acc = fmaf(wj[2], S[2][c], acc);
            np_sh[al * 33 + vg * 8 + c] = acc;
        }
    }
    __syncthreads();

    // finish cosine: 512 (a,c) tasks
    for (int idx = t; idx < 512; idx += 256) {
        int aa = idx >> 3, cc = idx & 7;
        float wv[NV];
#pragma unroll
        for (int v = 0; v < NV; v++) wv[v] = w_sh[aa * NV + v];
        float num = (np_sh[aa * 33 + cc] + np_sh[aa * 33 + 8 + cc]) +
                    (np_sh[aa * 33 + 16 + cc] + np_sh[aa * 33 + 24 + cc]);
        float den = 0.0f;
#pragma unroll
        for (int v1 = 0; v1 < NV; v1++) {
            float ds = 0.0f;
#pragma unroll
            for (int v2 = 0; v2 < NV; v2++)
                ds = fmaf(wv[v2], G_sh[cc * NV * NV + v1 * NV + v2], ds);
            den = fmaf(wv[v1], ds, den);
        }
        g_cos[(b * NA + a0 + aa) * NC + cc] = num * invn_sh[aa * NC + cc] * rsqrtf(den);
    }
    for (int i = t; i < 64 * NV; i += 256) g_w[(b * NA + a0) * NV + i] = w_sh[i];
}

// ================= kernel 3: MLP gating main loop (f32x2, depth-2 prefetch) =================
// grid (4, NB), 512 threads. warp = (center, half); lane owns h = 32*(half*4+j)+lane.
__global__ __launch_bounds__(512, 1) void k_main(const float* __restrict__ W2,
                                                 const float* __restrict__ b2,
                                                 float* __restrict__ out) {
    __shared__ __align__(16) float2 wd_sh[64 * NV];  // duplicated packed weights
    __shared__ float cos_sh[64 * NC];
    __shared__ float part_sh[64][16];

    const int t = threadIdx.x;
    const int b = blockIdx.y;
    const int a0 = blockIdx.x * 64;
    const int lane = t & 31, w16 = t >> 5;
    const int c = w16 >> 1, half = w16 & 1;

    for (int i = t; i < 64 * NV; i += 512) {
        float wv = g_w[(b * NA + a0) * NV + i];
        wd_sh[i] = make_float2(wv, wv);
    }
    for (int i = t; i < 64 * NC; i += 512) cos_sh[i] = g_cos[(b * NA + a0) * NC + i];

    unsigned long long pp[NV][2];
#pragma unroll
    for (int v = 0; v < NV; v++)
#pragma unroll
        for (int jp = 0; jp < 2; jp++) {
            const float* base = &g_P[((b * NV + v) * NC + c) * NH + lane];
            pp[v][jp] = pk2(base[32 * (half * 4 + 2 * jp)], base[32 * (half * 4 + 2 * jp + 1)]);
        }
    float w2r[4];
#pragma unroll
    for (int j = 0; j < 4; j++) w2r[j] = __ldg(&W2[32 * (half * 4 + j) + lane]);
    const float b2v = __ldg(&b2[0]);
    __syncthreads();

    const float* tb = g_T + (a0 * NC + c) * NH + lane * 8 + half * 4;
    ulonglong2 t0 = *(const ulonglong2*)tb;
    ulonglong2 t1 = *(const ulonglong2*)(tb + NC * NH);

#pragma unroll 2
    for (int ia = 0; ia < 64; ia++) {
        unsigned long long a01 = t0.x, a23 = t0.y;
        t0 = t1;
        int nia = (ia < 62) ? ia + 2 : 63;
        t1 = *(const ulonglong2*)(tb + nia * (NC * NH));  // prefetch distance 2

        const ulonglong2* wrow = (const ulonglong2*)&wd_sh[ia * NV];
#pragma unroll
        for (int vq = 0; vq < 6; vq++) {
            ulonglong2 wp = wrow[vq];
            a01 = ffma2(wp.x, pp[2 * vq][0], a01);
            a23 = ffma2(wp.x, pp[2 * vq][1], a23);
            a01 = ffma2(wp.y, pp[2 * vq + 1][0], a01);
            a23 = ffma2(wp.y, pp[2 * vq + 1][1], a23);
        }
        float f0, f1, f2, f3;
        upk2(a01, f0, f1); upk2(a23, f2, f3);
        float g = fmaxf(f0, 0.0f) * w2r[0];
        g = fmaf(fmaxf(f1, 0.0f), w2r[1], g);
        g = fmaf(fmaxf(f2, 0.0f), w2r[2], g);
        g = fmaf(fmaxf(f3, 0.0f), w2r[3], g);
#pragma unroll
        for (int off = 16; off; off >>= 1) g += __shfl_xor_sync(0xffffffffu, g, off);
        if (lane == 0) part_sh[ia][c * 2 + half] = g;
    }
    __syncthreads();

    if (t < 64) {
        float sum = 0.0f;
#pragma unroll
        for (int c2 = 0; c2 < NC; c2++)
            sum += (part_sh[t][2 * c2] + part_sh[t][2 * c2 + 1] + b2v) * cos_sh[t * NC + c2];
        out[(a0 + t) * NB + b] = sum;
    }
}

extern "C" void kernel_launch(void* const* d_in, const int* in_sizes, int n_in,
                              void* d_out, int out_size) {
    const float* text  = (const float*)d_in[0];
    const float* video = (const float*)d_in[1];
    const float* W1    = (const float*)d_in[2];
    const float* b1    = (const float*)d_in[3];
    const float* W2    = (const float*)d_in[4];
    const float* b2    = (const float*)d_in[5];
    float* out = (float*)d_out;

    cudaFuncSetAttribute(k_score, cudaFuncAttributeMaxDynamicSharedMemorySize,
                         SCORE_SMEM_BYTES);

    k_pre<<<NB * NV + NA + NB, 256>>>(text, video, W1, b1);
    k_score<<<dim3(4, NB), 256, SCORE_SMEM_BYTES>>>(text, video);
    k_main<<<dim3(4, NB), 512>>>(W2, b2, out);
}

// round 7
// speedup vs baseline: 1.9775x; 1.0446x over previous
#include <cuda_runtime.h>
#include <cstdint>

#define NA 256
#define NB 256
#define NV 12
#define ND 512
#define NC 8
#define NW 64
#define NH 256
#define TEMP_INV 0.2f

// ---- scratch (device globals; no allocation allowed) ----
__device__ __align__(16) float g_P[NB * NV * NC * NH];   // 25 MB [b][v][c][h]
__device__ __align__(16) float g_T[NA * NC * NH];        // 2 MB  [a][c][lane*8+k] packed
__device__ float g_invn[NA * NC];                        // 1/||t_chunk||
__device__ float g_G[NB * NC * NV * NV];                 // 1.2 MB chunk Gram
__device__ __align__(16) float g_w[NB * NA * NV];        // 3 MB softmax weights
__device__ __align__(16) float g_cos[NB * NA * NC];      // 2 MB cosine logits

// ---- packed f32x2 helpers ----
__device__ __forceinline__ unsigned long long pk2(float lo, float hi) {
    unsigned long long r;
    asm("mov.b64 %0, {%1, %2};" : "=l"(r) : "f"(lo), "f"(hi));
    return r;
}
__device__ __forceinline__ void upk2(unsigned long long p, float& lo, float& hi) {
    asm("mov.b64 {%0, %1}, %2;" : "=f"(lo), "=f"(hi) : "l"(p));
}
__device__ __forceinline__ unsigned long long ffma2(unsigned long long a, unsigned long long b,
                                                    unsigned long long c) {
    unsigned long long d;
    asm("fma.rn.f32x2 %0, %1, %2, %3;" : "=l"(d) : "l"(a), "l"(b), "l"(c));
    return d;
}
// warp-wide fp32 add reduction (portable shuffle butterfly)
__device__ __forceinline__ float warp_sum(float x) {
#pragma unroll
    for (int off = 16; off; off >>= 1) x += __shfl_xor_sync(0xffffffffu, x, off);
    return x;
}

// ---- cp.async helpers ----
__device__ __forceinline__ void cp16(uint32_t dst_smem, const void* src) {
    asm volatile("cp.async.cg.shared.global [%0], [%1], 16;" :: "r"(dst_smem), "l"(src));
}
__device__ __forceinline__ void cp_commit() {
    asm volatile("cp.async.commit_group;");
}
template <int N>
__device__ __forceinline__ void cp_wait() {
    asm volatile("cp.async.wait_group %0;" :: "n"(N));
}

// ================= kernel 1: prologue =================
// blocks [0,NB): per-video b — P for all 12 frames (w1p register-resident) + Gram.
// blocks [NB,NB+NA): per-text a — Tpart packed + inverse norms.
__global__ __launch_bounds__(256, 2) void k_pre(const float* __restrict__ text,
                                                const float* __restrict__ video,
                                                const float* __restrict__ W1,
                                                const float* __restrict__ b1) {
    __shared__ __align__(16) float sm[NV * ND];  // 24 KB, aliased per role
    const int bid = blockIdx.x, t = threadIdx.x;

    if (bid < NB) {
        const int b = bid;
        // stage all 12 video rows once
        {
            const float4* vsrc = (const float4*)(video + b * NV * ND);
            float4* vdst = (float4*)sm;
            for (int i = t; i < NV * ND / 4; i += 256) vdst[i] = __ldg(vsrc + i);
        }
        __syncthreads();

        // W1 video column for hidden unit t, packed over w — loaded ONCE per block
        unsigned long long w1p[NW / 2];
#pragma unroll
        for (int w = 0; w < NW / 2; w++)
            w1p[w] = pk2(__ldg(&W1[(NW + 2 * w) * NH + t]),
                         __ldg(&W1[(NW + 2 * w + 1) * NH + t]));

        for (int v = 0; v < NV; v++) {
#pragma unroll
            for (int c = 0; c < NC; c++) {
                unsigned long long accA = 0ULL, accB = 0ULL;
                const ulonglong2* vr = (const ulonglong2*)(sm + v * ND + c * NW);
#pragma unroll
                for (int q = 0; q < NW / 4; q++) {
                    ulonglong2 x = vr[q];
                    accA = ffma2(x.x, w1p[2 * q], accA);
                    accB = ffma2(x.y, w1p[2 * q + 1], accB);
                }
                float a0, a1, b0, b1;
                upk2(accA, a0, a1); upk2(accB, b0, b1);
                g_P[((b * NV + v) * NC + c) * NH + t] = (a0 + b0) + (a1 + b1);
            }
        }

        // Gram from the staged video rows
        for (int idx = t; idx < NC * NV * NV; idx += 256) {
            int c  = idx / (NV * NV);
            int r  = idx % (NV * NV);
            int v1 = r / NV, v2 = r % NV;
            const float* p1 = sm + v1 * ND + c * NW;
            const float* p2 = sm + v2 * ND + c * NW;
            float acc = 0.0f;
#pragma unroll
            for (int w = 0; w < NW; w++) acc = fmaf(p1[w], p2[w], acc);
            g_G[b * NC * NV * NV + idx] = acc;
        }
    } else {
        // ---- text path: Tpart packed + inverse norms ----
        const int a = bid - NB;
        float* trow  = sm;        // 512 floats
        float* stage = sm + 512;  // 8*264 floats
        trow[t]       = text[a * ND + t];
        trow[t + 256] = text[a * ND + 256 + t];
        __syncthreads();

        float w1t[NW];
#pragma unroll
        for (int w = 0; w < NW; w++) w1t[w] = __ldg(&W1[w * NH + t]);
        const float bb = __ldg(&b1[t]);
        const int kk = t >> 5, lane = t & 31;

#pragma unroll
        for (int c = 0; c < NC; c++) {
            float acc = bb;
#pragma unroll
            for (int w = 0; w < NW; w++) acc = fmaf(trow[c * NW + w], w1t[w], acc);
            stage[c * 264 + kk * 33 + lane] = acc;
        }

        float x1 = trow[kk * NW + lane];
        float x2 = trow[kk * NW + 32 + lane];
        float s = warp_sum(x1 * x1 + x2 * x2);
        if (lane == 0) g_invn[a * NC + kk] = rsqrtf(s);
        __syncthreads();

        for (int i = t; i < NC * NH; i += 256) {
            int c = i >> 8, r = i & 255;
            g_T[a * (NC * NH) + i] = stage[c * 264 + (r & 7) * 33 + (r >> 3)];
        }
    }
}

// ================= kernel 2: scores + softmax + cosine (cp.async pipelined) =================
// grid (4, NB), 256 threads. Thread = (al = t&63, vg = t>>6); vg covers frames 3vg..3vg+2.
#define TROW 68
#define TBUF (64 * TROW)  // 4352 floats per buffer
#define SCORE_SMEM_BYTES (20224 * 4)

__global__ __launch_bounds__(256, 2) void k_score(const float* __restrict__ text,
                                                  const float* __restrict__ video) {
    extern __shared__ __align__(16) float dyn[];
    float* T_sh    = dyn;
    float* V_sh    = dyn + 8704;
    float* G_sh    = dyn + 14848;
    float* w_sh    = dyn + 16000;
    float* invn_sh = dyn + 16768;
    float* logit_sh= dyn + 17280;
    float* np_sh   = dyn + 18112;

    const int t = threadIdx.x;
    const int b = blockIdx.y;
    const int a0 = blockIdx.x * 64;
    const int al = t & 63, vg = t >> 6;

    const int lrow = t >> 2, lpart = t & 3;
    const float* tg = text + (a0 + lrow) * ND + lpart * 16;
    uint32_t ts_addr[2];
#pragma unroll
    for (int bu = 0; bu < 2; bu++)
        ts_addr[bu] = (uint32_t)__cvta_generic_to_shared(
            &T_sh[bu * TBUF + lrow * TROW + lpart * 16]);

#pragma unroll
    for (int k = 0; k < 4; k++) cp16(ts_addr[0] + k * 16, tg + k * 4);
    cp_commit();

    {
        const float4* vsrc = (const float4*)(video + b * NV * ND);
        float4* vdst = (float4*)V_sh;
        for (int i = t; i < NV * ND / 4; i += 256) vdst[i] = __ldg(vsrc + i);
    }
    for (int i = t; i < NC * NV * NV; i += 256) G_sh[i] = g_G[b * NC * NV * NV + i];
    for (int i = t; i < 64 * NC; i += 256) invn_sh[i] = g_invn[a0 * NC + i];

    float S[3][NC];
#pragma unroll
    for (int c = 0; c < NC; c++) {
        if (c < 7) {
#pragma unroll
            for (int k = 0; k < 4; k++)
                cp16(ts_addr[(c + 1) & 1] + k * 16, tg + (c + 1) * 64 + k * 4);
            cp_commit();
            cp_wait<1>();
        } else {
            cp_wait<0>();
        }
        __syncthreads();

        const float* Tb = T_sh + (c & 1) * TBUF;
        unsigned long long accA[3] = {0ULL, 0ULL, 0ULL};
        unsigned long long accB[3] = {0ULL, 0ULL, 0ULL};
#pragma unroll
        for (int q = 0; q < 16; q++) {
            ulonglong2 tr = *(const ulonglong2*)&Tb[al * TROW + q * 4];
#pragma unroll
            for (int j = 0; j < 3; j++) {
                ulonglong2 vd = *(const ulonglong2*)&V_sh[(vg * 3 + j) * ND + c * NW + q * 4];
                accA[j] = ffma2(tr.x, vd.x, accA[j]);
                accB[j] = ffma2(tr.y, vd.y, accB[j]);
            }
        }
#pragma unroll
        for (int j = 0; j < 3; j++) {
            float x0, x1, y0, y1;
            upk2(accA[j], x0, x1); upk2(accB[j], y0, y1);
            S[j][c] = (x0 + y0) + (x1 + y1);
        }
        __syncthreads();
    }

#pragma unroll
    for (int j = 0; j < 3; j++) {
        float l = 0.0f;
#pragma unroll
        for (int c = 0; c < NC; c++) l += S[j][c];
        logit_sh[al * 13 + vg * 3 + j] = l;
    }
    __syncthreads();

    if (t < 64) {
        float s[NV], m = -1e30f;
#pragma unroll
        for (int v = 0; v < NV; v++) {
            s[v] = logit_sh[t * 13 + v] * TEMP_INV;
            m = fmaxf(m, s[v]);
        }
        float tot = 0.0f;
#pragma unroll
        for (int v = 0; v < NV; v++) { s[v] = __expf(s[v] - m); tot += s[v]; }
        float inv = 1.0f / tot;
#pragma unroll
        for (int v = 0; v < NV; v++) w_sh[t * NV + v] = s[v] * inv;
    }
    __syncthreads();

    {
        float wj[3];
#pragma unroll
        for (int j = 0; j < 3; j++) wj[j] = w_sh[al * NV + vg * 3 + j];
#pragma unroll
        for (int c = 0; c < NC; c++) {
            float acc = wj[0] * S[0][c];
            acc = fmaf(wj[1], S[1][c], acc);
            acc = fmaf(wj[2], S[2][c], acc);
            np_sh[al * 33 + vg * 8 + c] = acc;
        }
    }
    __syncthreads();

    for (int idx = t; idx < 512; idx += 256) {
        int aa = idx >> 3, cc = idx & 7;
        float wv[NV];
#pragma unroll
        for (int v = 0; v < NV; v++) wv[v] = w_sh[aa * NV + v];
        float num = (np_sh[aa * 33 + cc] + np_sh[aa * 33 + 8 + cc]) +
                    (np_sh[aa * 33 + 16 + cc] + np_sh[aa * 33 + 24 + cc]);
        float den = 0.0f;
#pragma unroll
        for (int v1 = 0; v1 < NV; v1++) {
            float ds = 0.0f;
#pragma unroll
            for (int v2 = 0; v2 < NV; v2++)
                ds = fmaf(wv[v2], G_sh[cc * NV * NV + v1 * NV + v2], ds);
            den = fmaf(wv[v1], ds, den);
        }
        g_cos[(b * NA + a0 + aa) * NC + cc] = num * invn_sh[aa * NC + cc] * rsqrtf(den);
    }
    for (int i = t; i < 64 * NV; i += 256) g_w[(b * NA + a0) * NV + i] = w_sh[i];
}

// ================= kernel 3: MLP gating main loop (f32x2, depth-2 prefetch) =================
__global__ __launch_bounds__(512, 1) void k_main(const float* __restrict__ W2,
                                                 const float* __restrict__ b2,
                                                 float* __restrict__ out) {
    __shared__ __align__(16) float2 wd_sh[64 * NV];
    __shared__ float cos_sh[64 * NC];
    __shared__ float part_sh[64][16];

    const int t = threadIdx.x;
    const int b = blockIdx.y;
    const int a0 = blockIdx.x * 64;
    const int lane = t & 31, w16 = t >> 5;
    const int c = w16 >> 1, half = w16 & 1;

    for (int i = t; i < 64 * NV; i += 512) {
        float wv = g_w[(b * NA + a0) * NV + i];
        wd_sh[i] = make_float2(wv, wv);
    }
    for (int i = t; i < 64 * NC; i += 512) cos_sh[i] = g_cos[(b * NA + a0) * NC + i];

    unsigned long long pp[NV][2];
#pragma unroll
    for (int v = 0; v < NV; v++)
#pragma unroll
        for (int jp = 0; jp < 2; jp++) {
            const float* base = &g_P[((b * NV + v) * NC + c) * NH + lane];
            pp[v][jp] = pk2(base[32 * (half * 4 + 2 * jp)], base[32 * (half * 4 + 2 * jp + 1)]);
        }
    float w2r[4];
#pragma unroll
    for (int j = 0; j < 4; j++) w2r[j] = __ldg(&W2[32 * (half * 4 + j) + lane]);
    const float b2v = __ldg(&b2[0]);
    __syncthreads();

    const float* tb = g_T + (a0 * NC + c) * NH + lane * 8 + half * 4;
    ulonglong2 t0 = *(const ulonglong2*)tb;
    ulonglong2 t1 = *(const ulonglong2*)(tb + NC * NH);

#pragma unroll 2
    for (int ia = 0; ia < 64; ia++) {
        unsigned long long a01 = t0.x, a23 = t0.y;
        t0 = t1;
        int nia = (ia < 62) ? ia + 2 : 63;
        t1 = *(const ulonglong2*)(tb + nia * (NC * NH));

        const ulonglong2* wrow = (const ulonglong2*)&wd_sh[ia * NV];
#pragma unroll
        for (int vq = 0; vq < 6; vq++) {
            ulonglong2 wp = wrow[vq];
            a01 = ffma2(wp.x, pp[2 * vq][0], a01);
            a23 = ffma2(wp.x, pp[2 * vq][1], a23);
            a01 = ffma2(wp.y, pp[2 * vq + 1][0], a01);
            a23 = ffma2(wp.y, pp[2 * vq + 1][1], a23);
        }
        float f0, f1, f2, f3;
        upk2(a01, f0, f1); upk2(a23, f2, f3);
        float g = fmaxf(f0, 0.0f) * w2r[0];
        g = fmaf(fmaxf(f1, 0.0f), w2r[1], g);
        g = fmaf(fmaxf(f2, 0.0f), w2r[2], g);
        g = fmaf(fmaxf(f3, 0.0f), w2r[3], g);
        g = warp_sum(g);
        if (lane == 0) part_sh[ia][c * 2 + half] = g;
    }
    __syncthreads();

    if (t < 64) {
        float sum = 0.0f;
#pragma unroll
        for (int c2 = 0; c2 < NC; c2++)
            sum += (part_sh[t][2 * c2] + part_sh[t][2 * c2 + 1] + b2v) * cos_sh[t * NC + c2];
        out[(a0 + t) * NB + b] = sum;
    }
}

extern "C" void kernel_launch(void* const* d_in, const int* in_sizes, int n_in,
                              void* d_out, int out_size) {
    const float* text  = (const float*)d_in[0];
    const float* video = (const float*)d_in[1];
    const float* W1    = (const float*)d_in[2];
    const float* b1    = (const float*)d_in[3];
    const float* W2    = (const float*)d_in[4];
    const float* b2    = (const float*)d_in[5];
    float* out = (float*)d_out;

    cudaFuncSetAttribute(k_score, cudaFuncAttributeMaxDynamicSharedMemorySize,
                         SCORE_SMEM_BYTES);

    k_pre<<<NB + NA, 256>>>(text, video, W1, b1);
    k_score<<<dim3(4, NB), 256, SCORE_SMEM_BYTES>>>(text, video);
    k_main<<<dim3(4, NB), 512>>>(W2, b2, out);
}